// round 4
// baseline (speedup 1.0000x reference)
#include <cuda_runtime.h>
#include <math.h>
#include <stdint.h>

// Problem dims (fixed by the dataset)
#define NROWS 8192   // B*L = 4*2048
#define DIN   1536
#define DH    4096
#define DOUT  2048
#define KCB   8192

// Scratch (allocation-free rule: __device__ globals)
__device__ float g_h[(size_t)NROWS * DH];     // 128 MB
__device__ float g_z[(size_t)NROWS * DOUT];   // 64 MB
__device__ float g_s1[NROWS];
__device__ float g_s2[KCB];
__device__ unsigned long long g_best[NROWS];

// ---------------------------------------------------------------------------
// Block reduction helper (256 threads)
// ---------------------------------------------------------------------------
__device__ __forceinline__ float block_reduce_sum_256(float v, float* sbuf) {
    __syncthreads();  // protect sbuf reuse across successive calls
    const int lane = threadIdx.x & 31;
    const int w    = threadIdx.x >> 5;
#pragma unroll
    for (int o = 16; o > 0; o >>= 1) v += __shfl_xor_sync(0xffffffffu, v, o);
    if (lane == 0) sbuf[w] = v;
    __syncthreads();
    float r = (lane < 8) ? sbuf[lane] : 0.0f;
    if (w == 0) {
#pragma unroll
        for (int o = 4; o > 0; o >>= 1) r += __shfl_xor_sync(0xffffffffu, r, o);
        if (lane == 0) sbuf[8] = r;
    }
    __syncthreads();
    return sbuf[8];
}

// ---------------------------------------------------------------------------
// fp32 NT GEMM: C[m,n] = sum_k A[m,k]*B[n,k] + bias[n]
// BM=BN=128, BK=8, 256 threads, 8x8 per thread, double-buffered smem
// ---------------------------------------------------------------------------
__global__ __launch_bounds__(256, 2)
void gemm_nt_bias(const float* __restrict__ A, const float* __restrict__ B,
                  const float* __restrict__ bias, float* __restrict__ C,
                  int M, int N, int K)
{
    __shared__ float As[2][8][132];
    __shared__ float Bs[2][8][132];

    const int tid = threadIdx.x;
    const int tx  = tid & 15;
    const int ty  = tid >> 4;
    const int lr  = tid >> 1;        // 0..127 row within tile
    const int lc  = (tid & 1) << 2;  // 0 or 4 (k chunk)

    const float* Ab = A + (size_t)blockIdx.y * 128 * K;
    const float* Bb = B + (size_t)blockIdx.x * 128 * K;

    float acc[8][8];
#pragma unroll
    for (int i = 0; i < 8; i++)
#pragma unroll
        for (int j = 0; j < 8; j++) acc[i][j] = 0.0f;

    float4 a4 = *(const float4*)(Ab + (size_t)lr * K + lc);
    float4 b4 = *(const float4*)(Bb + (size_t)lr * K + lc);
    As[0][lc + 0][lr] = a4.x; As[0][lc + 1][lr] = a4.y;
    As[0][lc + 2][lr] = a4.z; As[0][lc + 3][lr] = a4.w;
    Bs[0][lc + 0][lr] = b4.x; Bs[0][lc + 1][lr] = b4.y;
    Bs[0][lc + 2][lr] = b4.z; Bs[0][lc + 3][lr] = b4.w;
    __syncthreads();

    const int nk = K >> 3;
    for (int kt = 0; kt < nk; kt++) {
        const int cur = kt & 1;
        const bool more = (kt + 1 < nk);
        if (more) {
            const int ko = ((kt + 1) << 3) + lc;
            a4 = *(const float4*)(Ab + (size_t)lr * K + ko);
            b4 = *(const float4*)(Bb + (size_t)lr * K + ko);
        }
#pragma unroll
        for (int kk = 0; kk < 8; kk++) {
            float ar[8], br[8];
            *(float4*)&ar[0] = *(const float4*)&As[cur][kk][ty * 8];
            *(float4*)&ar[4] = *(const float4*)&As[cur][kk][ty * 8 + 4];
            *(float4*)&br[0] = *(const float4*)&Bs[cur][kk][tx * 8];
            *(float4*)&br[4] = *(const float4*)&Bs[cur][kk][tx * 8 + 4];
#pragma unroll
            for (int i = 0; i < 8; i++)
#pragma unroll
                for (int j = 0; j < 8; j++)
                    acc[i][j] = fmaf(ar[i], br[j], acc[i][j]);
        }
        if (more) {
            const int nxt = cur ^ 1;
            As[nxt][lc + 0][lr] = a4.x; As[nxt][lc + 1][lr] = a4.y;
            As[nxt][lc + 2][lr] = a4.z; As[nxt][lc + 3][lr] = a4.w;
            Bs[nxt][lc + 0][lr] = b4.x; Bs[nxt][lc + 1][lr] = b4.y;
            Bs[nxt][lc + 2][lr] = b4.z; Bs[nxt][lc + 3][lr] = b4.w;
        }
        __syncthreads();
    }

    const int row0 = blockIdx.y * 128 + ty * 8;
    const int col0 = blockIdx.x * 128 + tx * 8;
#pragma unroll
    for (int i = 0; i < 8; i++) {
        float* Cp = C + (size_t)(row0 + i) * N + col0;
#pragma unroll
        for (int j = 0; j < 8; j++)
            Cp[j] = __fadd_rn(acc[i][j], bias[col0 + j]);
    }
}

// ---------------------------------------------------------------------------
// Distance GEMM + fused argmin:
//   m = z_row . c_k  over K=2048
//   d = fl( fl(s1[row] + s2[k]) - 2*m )   (replicates reference fp32 rounding)
//   argmin with first-index tie-break via u64 key min
// ---------------------------------------------------------------------------
__global__ __launch_bounds__(256, 2)
void dist_argmin(const float* __restrict__ A, const float* __restrict__ B,
                 const float* __restrict__ s1, const float* __restrict__ s2,
                 unsigned long long* __restrict__ best,
                 int M, int N, int K)
{
    __shared__ float As[2][8][132];
    __shared__ float Bs[2][8][132];
    __shared__ unsigned long long red[128][17];

    const int tid = threadIdx.x;
    const int tx  = tid & 15;
    const int ty  = tid >> 4;
    const int lr  = tid >> 1;
    const int lc  = (tid & 1) << 2;

    const float* Ab = A + (size_t)blockIdx.y * 128 * K;
    const float* Bb = B + (size_t)blockIdx.x * 128 * K;

    float acc[8][8];
#pragma unroll
    for (int i = 0; i < 8; i++)
#pragma unroll
        for (int j = 0; j < 8; j++) acc[i][j] = 0.0f;

    float4 a4 = *(const float4*)(Ab + (size_t)lr * K + lc);
    float4 b4 = *(const float4*)(Bb + (size_t)lr * K + lc);
    As[0][lc + 0][lr] = a4.x; As[0][lc + 1][lr] = a4.y;
    As[0][lc + 2][lr] = a4.z; As[0][lc + 3][lr] = a4.w;
    Bs[0][lc + 0][lr] = b4.x; Bs[0][lc + 1][lr] = b4.y;
    Bs[0][lc + 2][lr] = b4.z; Bs[0][lc + 3][lr] = b4.w;
    __syncthreads();

    const int nk = K >> 3;
    for (int kt = 0; kt < nk; kt++) {
        const int cur = kt & 1;
        const bool more = (kt + 1 < nk);
        if (more) {
            const int ko = ((kt + 1) << 3) + lc;
            a4 = *(const float4*)(Ab + (size_t)lr * K + ko);
            b4 = *(const float4*)(Bb + (size_t)lr * K + ko);
        }
#pragma unroll
        for (int kk = 0; kk < 8; kk++) {
            float ar[8], br[8];
            *(float4*)&ar[0] = *(const float4*)&As[cur][kk][ty * 8];
            *(float4*)&ar[4] = *(const float4*)&As[cur][kk][ty * 8 + 4];
            *(float4*)&br[0] = *(const float4*)&Bs[cur][kk][tx * 8];
            *(float4*)&br[4] = *(const float4*)&Bs[cur][kk][tx * 8 + 4];
#pragma unroll
            for (int i = 0; i < 8; i++)
#pragma unroll
                for (int j = 0; j < 8; j++)
                    acc[i][j] = fmaf(ar[i], br[j], acc[i][j]);
        }
        if (more) {
            const int nxt = cur ^ 1;
            As[nxt][lc + 0][lr] = a4.x; As[nxt][lc + 1][lr] = a4.y;
            As[nxt][lc + 2][lr] = a4.z; As[nxt][lc + 3][lr] = a4.w;
            Bs[nxt][lc + 0][lr] = b4.x; Bs[nxt][lc + 1][lr] = b4.y;
            Bs[nxt][lc + 2][lr] = b4.z; Bs[nxt][lc + 3][lr] = b4.w;
        }
        __syncthreads();
    }

    const int row0 = blockIdx.y * 128;
    const int col0 = blockIdx.x * 128 + tx * 8;
    float s1r[8], s2c[8];
#pragma unroll
    for (int i = 0; i < 8; i++) s1r[i] = s1[row0 + ty * 8 + i];
#pragma unroll
    for (int j = 0; j < 8; j++) s2c[j] = s2[col0 + j];

#pragma unroll
    for (int i = 0; i < 8; i++) {
        unsigned long long bk = ~0ull;
#pragma unroll
        for (int j = 0; j < 8; j++) {
            // Reference: d = fl(fl(s1+s2) - fl(2*m)); 2*m is exact in fp32.
            float t = __fadd_rn(s1r[i], s2c[j]);
            float d = __fsub_rn(t, 2.0f * acc[i][j]);
            unsigned long long key =
                ((unsigned long long)__float_as_uint(d) << 32) |
                (unsigned int)(col0 + j);
            bk = (key < bk) ? key : bk;
        }
        red[ty * 8 + i][tx] = bk;
    }
    __syncthreads();
    if (tid < 128) {
        unsigned long long b = red[tid][0];
#pragma unroll
        for (int x = 1; x < 16; x++) {
            unsigned long long c = red[tid][x];
            b = (c < b) ? c : b;
        }
        atomicMin(&best[row0 + tid], b);
    }
}

// ---------------------------------------------------------------------------
// LayerNorm (+optional exact GELU, +optional sum(z^2) output), in place
// ---------------------------------------------------------------------------
template<int W, bool DO_GELU, bool WRITE_S1>
__global__ void ln_kernel(float* __restrict__ X,
                          const float* __restrict__ gw,
                          const float* __restrict__ bw,
                          float* __restrict__ s1out)
{
    constexpr int T = 256;
    constexpr int P = W / T;
    __shared__ float sbuf[9];
    const int tid = threadIdx.x;
    float* xp = X + (size_t)blockIdx.x * W;

    float v[P];
#pragma unroll
    for (int i = 0; i < P; i++) v[i] = xp[tid + i * T];

    float s = 0.0f;
#pragma unroll
    for (int i = 0; i < P; i++) s += v[i];
    s = block_reduce_sum_256(s, sbuf);
    const float mu = s * (1.0f / (float)W);   // W is a power of two: exact

    float vs = 0.0f;
#pragma unroll
    for (int i = 0; i < P; i++) { float d = v[i] - mu; vs = fmaf(d, d, vs); }
    vs = block_reduce_sum_256(vs, sbuf);
    const float var = vs * (1.0f / (float)W);
    const float rs = 1.0f / sqrtf(var + 1e-5f);

    float acc = 0.0f;
#pragma unroll
    for (int i = 0; i < P; i++) {
        const int c = tid + i * T;
        float y = (v[i] - mu) * rs;
        y = __fadd_rn(__fmul_rn(y, gw[c]), bw[c]);
        if (DO_GELU) y = 0.5f * y * (1.0f + erff(y * 0.7071067811865476f));
        xp[c] = y;
        if (WRITE_S1) acc = fmaf(y, y, acc);
    }
    if (WRITE_S1) {
        acc = block_reduce_sum_256(acc, sbuf);
        if (tid == 0) s1out[blockIdx.x] = acc;
    }
}

// ---------------------------------------------------------------------------
// |c_k|^2 per codebook row; blocks 0..NROWS/256-1 also reset g_best
// ---------------------------------------------------------------------------
__global__ void c2_init_kernel(const float* __restrict__ cb,
                               float* __restrict__ s2)
{
    __shared__ float sbuf[9];
    const int gidx = blockIdx.x * 256 + threadIdx.x;
    if (gidx < NROWS) g_best[gidx] = ~0ull;

    const float* cp = cb + (size_t)blockIdx.x * DOUT;
    float a = 0.0f;
    for (int i = threadIdx.x; i < DOUT; i += 256) {
        float c = cp[i];
        a = fmaf(c, c, a);
    }
    a = block_reduce_sum_256(a, sbuf);
    if (threadIdx.x == 0) s2[blockIdx.x] = a;
}

// Output = codebook[idx] (forward value of the STE)
__global__ void gather_kernel(const float* __restrict__ cb,
                              float* __restrict__ out)
{
    const int n = blockIdx.x;
    const unsigned int idx = (unsigned int)(g_best[n] & 0xffffffffu);
    const float* q = cb + (size_t)idx * DOUT;
    float* op = out + (size_t)n * DOUT;
    for (int d = threadIdx.x; d < DOUT; d += 256) op[d] = q[d];
}

// ---------------------------------------------------------------------------
extern "C" void kernel_launch(void* const* d_in, const int* in_sizes, int n_in,
                              void* d_out, int out_size)
{
    (void)in_sizes; (void)n_in; (void)out_size;
    const float* latents  = (const float*)d_in[0];
    const float* W1       = (const float*)d_in[1];
    const float* b1       = (const float*)d_in[2];
    const float* g1       = (const float*)d_in[3];
    const float* be1      = (const float*)d_in[4];
    const float* W2       = (const float*)d_in[5];
    const float* b2       = (const float*)d_in[6];
    const float* g2       = (const float*)d_in[7];
    const float* be2      = (const float*)d_in[8];
    const float* codebook = (const float*)d_in[9];
    float* out = (float*)d_out;

    // Resolve scratch addresses once (capture-safe: no stream work enqueued).
    static float* h  = nullptr;
    static float* z  = nullptr;
    static float* s1 = nullptr;
    static float* s2 = nullptr;
    static unsigned long long* best = nullptr;
    if (!h) {
        void* p;
        cudaGetSymbolAddress(&p, g_h);    h  = (float*)p;
        cudaGetSymbolAddress(&p, g_z);    z  = (float*)p;
        cudaGetSymbolAddress(&p, g_s1);   s1 = (float*)p;
        cudaGetSymbolAddress(&p, g_s2);   s2 = (float*)p;
        cudaGetSymbolAddress(&p, g_best); best = (unsigned long long*)p;
    }

    // |c|^2 per codeword + g_best reset (one launch)
    c2_init_kernel<<<KCB, 256>>>(codebook, s2);

    // h = latents @ W1^T + b1
    gemm_nt_bias<<<dim3(DH / 128, NROWS / 128), 256>>>(latents, W1, b1, h,
                                                       NROWS, DH, DIN);
    // h = gelu(layernorm(h))
    ln_kernel<DH, true, false><<<NROWS, 256>>>(h, g1, be1, nullptr);

    // z = h @ W2^T + b2
    gemm_nt_bias<<<dim3(DOUT / 128, NROWS / 128), 256>>>(h, W2, b2, z,
                                                         NROWS, DOUT, DH);
    // z = layernorm(z); s1 = sum(z^2) per row
    ln_kernel<DOUT, false, true><<<NROWS, 256>>>(z, g2, be2, s1);

    // fused distance + argmin
    dist_argmin<<<dim3(KCB / 128, NROWS / 128), 256>>>(z, codebook, s1, s2,
                                                       best, NROWS, KCB, DOUT);
    // out = codebook[idx]
    gather_kernel<<<NROWS, 256>>>(codebook, out);
}

// round 11
// speedup vs baseline: 1.6030x; 1.6030x over previous
#include <cuda_runtime.h>
#include <cuda_bf16.h>
#include <math.h>
#include <stdint.h>

// Problem dims (fixed by the dataset)
#define NROWS 8192   // B*L = 4*2048
#define DIN   1536
#define DH    4096
#define DOUT  2048
#define KCB   8192
#define CAND_CAP 64

// Scratch (allocation-free rule: __device__ globals)
__device__ float g_h[(size_t)NROWS * DH];     // 128 MB
__device__ float g_z[(size_t)NROWS * DOUT];   // 64 MB
__device__ float g_m[(size_t)NROWS * KCB];    // 256 MB (approx dot products)
__device__ float g_s1[NROWS];
__device__ float g_s2[KCB];
__device__ unsigned int g_rowmax[NROWS];      // order-encoded float max of m
__device__ int g_cnt[NROWS];
__device__ int g_cand[(size_t)NROWS * CAND_CAP];
__device__ unsigned long long g_best[NROWS];

// Candidate threshold margin: winner satisfies m >= max - 2.6e-4 (two fp32
// roundings of d at ~2048 scale + s2 spread) minus approx error ~3e-6.
#define TAU 4.0e-4f

// ---------------------------------------------------------------------------
// order-monotone float <-> uint encoding (for atomicMax on floats of any sign)
// ---------------------------------------------------------------------------
__device__ __forceinline__ unsigned int fkey(float x) {
    unsigned int u = __float_as_uint(x);
    return (u & 0x80000000u) ? ~u : (u | 0x80000000u);
}
__device__ __forceinline__ float funkey(unsigned int k) {
    unsigned int u = (k & 0x80000000u) ? (k ^ 0x80000000u) : ~k;
    return __uint_as_float(u);
}

// ---------------------------------------------------------------------------
// bf16 helpers: exact 3-way split  x = b0 + b1 + b2  (fp32 bit-exact)
// ---------------------------------------------------------------------------
__device__ __forceinline__ uint16_t bf16u(float x) {
    return __bfloat16_as_ushort(__float2bfloat16_rn(x));
}
__device__ __forceinline__ float ubf(uint16_t u) {
    return __uint_as_float(((uint32_t)u) << 16);
}
struct BSplit { uint16_t u[3]; };
__device__ __forceinline__ BSplit bsplit(float x) {
    BSplit r;
    r.u[0] = bf16u(x);
    const float r1 = __fsub_rn(x, ubf(r.u[0]));
    r.u[1] = bf16u(r1);
    const float r2 = __fsub_rn(r1, ubf(r.u[1]));
    r.u[2] = bf16u(r2);   // exact: r2 has <= 8 significand bits
    return r;
}
__device__ __forceinline__ uint32_t pack2(uint16_t lo, uint16_t hi) {
    return (uint32_t)lo | ((uint32_t)hi << 16);
}

__device__ __forceinline__ void mma_bf16(float acc[4], const uint32_t a[4],
                                         uint32_t b0, uint32_t b1) {
    asm volatile(
        "mma.sync.aligned.m16n8k16.row.col.f32.bf16.bf16.f32 "
        "{%0,%1,%2,%3}, {%4,%5,%6,%7}, {%8,%9}, {%0,%1,%2,%3};"
        : "+f"(acc[0]), "+f"(acc[1]), "+f"(acc[2]), "+f"(acc[3])
        : "r"(a[0]), "r"(a[1]), "r"(a[2]), "r"(a[3]), "r"(b0), "r"(b1));
}

// ---------------------------------------------------------------------------
// BF16-split tensor-core GEMM via mma.sync.
//   !IS_M2: 6 passes (fp32-grade) -> C = A@B^T + bias
//   IS_M2 : 3 passes (err ~3e-6)  -> g_m tile + per-row max (atomicMax)
//   CTA tile 128x128, BK=16, 256 thr, warp grid 2(m)x4(n), warp tile 64x32.
// ---------------------------------------------------------------------------
static constexpr int SA_U32 = 2 * 8 * 3 * 4 * 33;    // 6336
static constexpr int SB_U32 = 2 * 16 * 3 * 2 * 33;   // 6336
static constexpr int SMEM_DYN = (SA_U32 + SB_U32) * 4;  // 50688 B

template<int K, bool IS_M2>
__global__ __launch_bounds__(256)
void mma_gemm(const float* __restrict__ A, const float* __restrict__ B,
              const float* __restrict__ bias, float* __restrict__ C, int ldN,
              unsigned int* __restrict__ rowmax)
{
    extern __shared__ uint32_t sm[];
    uint32_t* sA = sm;
    uint32_t* sB = sm + SA_U32;

    const int tid  = threadIdx.x;
    const int lane = tid & 31;
    const int wid  = tid >> 5;
    const int wm   = wid >> 2;   // 0..1
    const int wn   = wid & 3;    // 0..3
    const int bm   = blockIdx.y;
    const int bn   = blockIdx.x;

    // Producer mapping: rows prow, prow+64 ; k-quad q (4 floats), h = q>>1
    const int prow = tid >> 2;          // 0..63
    const int q    = tid & 3;
    const int h    = q >> 1;            // k-half (reg-pair select)
    const int t0   = (2 * q) & 3;       // fragment t of first pair

    const float* Ag0 = A + (size_t)(bm * 128 + prow) * K + q * 4;
    const float* Ag1 = Ag0 + (size_t)64 * K;
    const float* Bg0 = B + (size_t)(bn * 128 + prow) * K + q * 4;
    const float* Bg1 = Bg0 + (size_t)64 * K;

    float acc[4][4][4];
#pragma unroll
    for (int i = 0; i < 4; i++)
#pragma unroll
        for (int j = 0; j < 4; j++)
#pragma unroll
            for (int r = 0; r < 4; r++) acc[i][j][r] = 0.0f;

    float4 pa[2], pb[2];
    pa[0] = *(const float4*)(Ag0);
    pa[1] = *(const float4*)(Ag1);
    pb[0] = *(const float4*)(Bg0);
    pb[1] = *(const float4*)(Bg1);

    const int NCH = K / 16;
    for (int ch = 0; ch < NCH; ch++) {
        const int st = ch & 1;
        // ---- producer: exact bf16 3-way split, scatter into fragment planes
#pragma unroll
        for (int rr = 0; rr < 2; rr++) {
            const int row   = prow + rr * 64;
            const int mtile = row >> 4;
            const int g     = row & 7;
            const int hl    = (row >> 3) & 1;
            const int laneA = g * 4 + t0;
            {
                const float4 v = pa[rr];
                BSplit e0 = bsplit(v.x), e1 = bsplit(v.y),
                       e2 = bsplit(v.z), e3 = bsplit(v.w);
                uint32_t* base = sA + (((st * 8 + mtile) * 3) * 4 + hl + 2 * h) * 33 + laneA;
#pragma unroll
                for (int s = 0; s < 3; s++) {
                    base[s * 4 * 33]     = pack2(e0.u[s], e1.u[s]);
                    base[s * 4 * 33 + 1] = pack2(e2.u[s], e3.u[s]);
                }
            }
            {
                const float4 v = pb[rr];
                BSplit e0 = bsplit(v.x), e1 = bsplit(v.y),
                       e2 = bsplit(v.z), e3 = bsplit(v.w);
                uint32_t* base = sB + (((st * 16 + (row >> 3)) * 3) * 2 + h) * 33 + laneA;
#pragma unroll
                for (int s = 0; s < 3; s++) {
                    base[s * 2 * 33]     = pack2(e0.u[s], e1.u[s]);
                    base[s * 2 * 33 + 1] = pack2(e2.u[s], e3.u[s]);
                }
            }
        }
        __syncthreads();
        // ---- prefetch next chunk (overlaps with MMA below)
        if (ch + 1 < NCH) {
            const int ko = (ch + 1) * 16;
            pa[0] = *(const float4*)(Ag0 + ko);
            pa[1] = *(const float4*)(Ag1 + ko);
            pb[0] = *(const float4*)(Bg0 + ko);
            pb[1] = *(const float4*)(Bg1 + ko);
        }
        // ---- consumer: passes grouped by A-split for fragment reuse.
        // 6-pass: sa0:{b0,b1,b2} sa1:{b0,b1} sa2:{b0}   (drops >=2^-24 terms)
        // 3-pass: sa0:{b0,b1}    sa1:{b0}               (drops >=2^-16 terms)
#pragma unroll
        for (int sa = 0; sa < 3; sa++) {
            const int nb = (IS_M2 ? 2 : 3) - sa;
            if (nb <= 0) break;
            uint32_t af[4][4];
#pragma unroll
            for (int mt = 0; mt < 4; mt++) {
                const uint32_t* p =
                    sA + (((st * 8 + wm * 4 + mt) * 3 + sa) * 4) * 33 + lane;
#pragma unroll
                for (int r = 0; r < 4; r++) af[mt][r] = p[r * 33];
            }
#pragma unroll
            for (int sb = 0; sb < 3; sb++) {
                if (sb >= nb) break;
                uint32_t bf_[4][2];
#pragma unroll
                for (int nt = 0; nt < 4; nt++) {
                    const uint32_t* p =
                        sB + (((st * 16 + wn * 4 + nt) * 3 + sb) * 2) * 33 + lane;
                    bf_[nt][0] = p[0];
                    bf_[nt][1] = p[33];
                }
#pragma unroll
                for (int mt = 0; mt < 4; mt++)
#pragma unroll
                    for (int nt = 0; nt < 4; nt++)
                        mma_bf16(acc[mt][nt], af[mt], bf_[nt][0], bf_[nt][1]);
            }
        }
    }

    // ---- epilogue (fragment c: rows g,g+8 ; cols 2t,2t+1)
    const int g = lane >> 2, t = lane & 3;
    if (!IS_M2) {
#pragma unroll
        for (int mt = 0; mt < 4; mt++) {
            const int row = bm * 128 + wm * 64 + mt * 16 + g;
#pragma unroll
            for (int nt = 0; nt < 4; nt++) {
                const int col = bn * 128 + wn * 32 + nt * 8 + t * 2;
                const float bb0 = __ldg(&bias[col]);
                const float bb1 = __ldg(&bias[col + 1]);
                float2 v0, v1;
                v0.x = __fadd_rn(acc[mt][nt][0], bb0);
                v0.y = __fadd_rn(acc[mt][nt][1], bb1);
                v1.x = __fadd_rn(acc[mt][nt][2], bb0);
                v1.y = __fadd_rn(acc[mt][nt][3], bb1);
                *(float2*)(C + (size_t)row * ldN + col)       = v0;
                *(float2*)(C + (size_t)(row + 8) * ldN + col) = v1;
            }
        }
    } else {
        // store m tile + per-row max
        __syncthreads();               // stage buffers no longer read
        float* red = (float*)sm;       // [128][4]
#pragma unroll
        for (int mt = 0; mt < 4; mt++) {
#pragma unroll
            for (int hl = 0; hl < 2; hl++) {
                const int rowc = wm * 64 + mt * 16 + hl * 8 + g;
                const int row  = bm * 128 + rowc;
                float mx = -1e30f;
#pragma unroll
                for (int nt = 0; nt < 4; nt++) {
                    const int col = bn * 128 + wn * 32 + nt * 8 + t * 2;
                    float2 v;
                    v.x = acc[mt][nt][hl * 2 + 0];
                    v.y = acc[mt][nt][hl * 2 + 1];
                    *(float2*)(C + (size_t)row * ldN + col) = v;
                    mx = fmaxf(mx, fmaxf(v.x, v.y));
                }
#pragma unroll
                for (int off = 1; off < 4; off <<= 1)
                    mx = fmaxf(mx, __shfl_xor_sync(0xffffffffu, mx, off));
                if (t == 0) red[rowc * 4 + wn] = mx;
            }
        }
        __syncthreads();
        if (tid < 128) {
            float b = red[tid * 4];
#pragma unroll
            for (int x = 1; x < 4; x++) b = fmaxf(b, red[tid * 4 + x]);
            atomicMax(&rowmax[bm * 128 + tid], fkey(b));
        }
    }
}

// ---------------------------------------------------------------------------
// Candidate selection: cols with m >= rowmax - TAU
// ---------------------------------------------------------------------------
__global__ void select_kernel()
{
    const int row = blockIdx.x;
    const float thr = funkey(g_rowmax[row]) - TAU;
    const float* mp = g_m + (size_t)row * KCB;
    for (int i = threadIdx.x * 4; i < KCB; i += 256 * 4) {
        const float4 v = *(const float4*)(mp + i);
        if (v.x >= thr) { int p = atomicAdd(&g_cnt[row], 1); if (p < CAND_CAP) g_cand[row * CAND_CAP + p] = i; }
        if (v.y >= thr) { int p = atomicAdd(&g_cnt[row], 1); if (p < CAND_CAP) g_cand[row * CAND_CAP + p] = i + 1; }
        if (v.z >= thr) { int p = atomicAdd(&g_cnt[row], 1); if (p < CAND_CAP) g_cand[row * CAND_CAP + p] = i + 2; }
        if (v.w >= thr) { int p = atomicAdd(&g_cnt[row], 1); if (p < CAND_CAP) g_cand[row * CAND_CAP + p] = i + 3; }
    }
}

// ---------------------------------------------------------------------------
// Exact rescoring: sequential k-ascending fp32 FMA chain (the empirically
// reference-matching accumulation style), d = fl(fl(s1+s2) - 2m),
// first-index tie-break via u64 key atomicMin.
// ---------------------------------------------------------------------------
__global__ void rescore_kernel(const float* __restrict__ cb)
{
    const int row = blockIdx.x;
    const int c   = threadIdx.x;
    int cnt = g_cnt[row];
    if (cnt > CAND_CAP) cnt = CAND_CAP;
    if (c >= cnt) return;
    const int col = g_cand[row * CAND_CAP + c];

    const float4* zp = (const float4*)(g_z + (size_t)row * DOUT);
    const float4* cp = (const float4*)(cb + (size_t)col * DOUT);
    float acc = 0.0f;
#pragma unroll 4
    for (int i = 0; i < DOUT / 4; i++) {
        const float4 a = __ldg(zp + i);
        const float4 b = __ldg(cp + i);
        acc = fmaf(a.x, b.x, acc);
        acc = fmaf(a.y, b.y, acc);
        acc = fmaf(a.z, b.z, acc);
        acc = fmaf(a.w, b.w, acc);
    }
    const float d = __fsub_rn(__fadd_rn(g_s1[row], g_s2[col]), 2.0f * acc);
    const unsigned long long key =
        ((unsigned long long)__float_as_uint(d) << 32) | (unsigned int)col;
    atomicMin(&g_best[row], key);
}

// ---------------------------------------------------------------------------
// Elementwise kernels
// ---------------------------------------------------------------------------
__device__ __forceinline__ float block_reduce_sum_256(float v, float* sbuf) {
    __syncthreads();
    const int lane = threadIdx.x & 31;
    const int w    = threadIdx.x >> 5;
#pragma unroll
    for (int o = 16; o > 0; o >>= 1) v += __shfl_xor_sync(0xffffffffu, v, o);
    if (lane == 0) sbuf[w] = v;
    __syncthreads();
    float r = (lane < 8) ? sbuf[lane] : 0.0f;
    if (w == 0) {
#pragma unroll
        for (int o = 4; o > 0; o >>= 1) r += __shfl_xor_sync(0xffffffffu, r, o);
        if (lane == 0) sbuf[8] = r;
    }
    __syncthreads();
    return sbuf[8];
}

template<int W, bool DO_GELU, bool WRITE_S1>
__global__ void ln_kernel(float* __restrict__ X,
                          const float* __restrict__ gw,
                          const float* __restrict__ bw,
                          float* __restrict__ s1out)
{
    constexpr int T = 256;
    constexpr int P = W / T;
    __shared__ float sbuf[9];
    const int tid = threadIdx.x;
    float* xp = X + (size_t)blockIdx.x * W;

    float v[P];
#pragma unroll
    for (int i = 0; i < P; i++) v[i] = xp[tid + i * T];

    float s = 0.0f;
#pragma unroll
    for (int i = 0; i < P; i++) s += v[i];
    s = block_reduce_sum_256(s, sbuf);
    const float mu = s * (1.0f / (float)W);

    float vs = 0.0f;
#pragma unroll
    for (int i = 0; i < P; i++) { float d = v[i] - mu; vs = fmaf(d, d, vs); }
    vs = block_reduce_sum_256(vs, sbuf);
    const float var = vs * (1.0f / (float)W);
    const float rs = 1.0f / sqrtf(var + 1e-5f);

    float acc = 0.0f;
#pragma unroll
    for (int i = 0; i < P; i++) {
        const int c = tid + i * T;
        float y = (v[i] - mu) * rs;
        y = __fadd_rn(__fmul_rn(y, gw[c]), bw[c]);
        if (DO_GELU) y = 0.5f * y * (1.0f + erff(y * 0.7071067811865476f));
        xp[c] = y;
        if (WRITE_S1) acc = fmaf(y, y, acc);
    }
    if (WRITE_S1) {
        acc = block_reduce_sum_256(acc, sbuf);
        if (tid == 0) s1out[blockIdx.x] = acc;
    }
}

__global__ void c2_init_kernel(const float* __restrict__ cb,
                               float* __restrict__ s2)
{
    __shared__ float sbuf[9];
    const int gidx = blockIdx.x * 256 + threadIdx.x;
    if (gidx < NROWS) {
        g_best[gidx]   = ~0ull;
        g_cnt[gidx]    = 0;
        g_rowmax[gidx] = 0u;
    }

    const float* cp = cb + (size_t)blockIdx.x * DOUT;
    float a = 0.0f;
    for (int i = threadIdx.x; i < DOUT; i += 256) {
        float c = cp[i];
        a = fmaf(c, c, a);
    }
    a = block_reduce_sum_256(a, sbuf);
    if (threadIdx.x == 0) s2[blockIdx.x] = a;
}

__global__ void gather_kernel(const float* __restrict__ cb,
                              float* __restrict__ out)
{
    const int n = blockIdx.x;
    const unsigned int idx = (unsigned int)(g_best[n] & 0xffffffffu);
    const float* q = cb + (size_t)idx * DOUT;
    float* op = out + (size_t)n * DOUT;
    for (int d = threadIdx.x; d < DOUT; d += 256) op[d] = q[d];
}

// ---------------------------------------------------------------------------
extern "C" void kernel_launch(void* const* d_in, const int* in_sizes, int n_in,
                              void* d_out, int out_size)
{
    (void)in_sizes; (void)n_in; (void)out_size;
    const float* latents  = (const float*)d_in[0];
    const float* W1       = (const float*)d_in[1];
    const float* b1       = (const float*)d_in[2];
    const float* g1       = (const float*)d_in[3];
    const float* be1      = (const float*)d_in[4];
    const float* W2       = (const float*)d_in[5];
    const float* b2       = (const float*)d_in[6];
    const float* g2       = (const float*)d_in[7];
    const float* be2      = (const float*)d_in[8];
    const float* codebook = (const float*)d_in[9];
    float* out = (float*)d_out;

    static float* h  = nullptr;
    static float* z  = nullptr;
    static float* mM = nullptr;
    static float* s1 = nullptr;
    static float* s2 = nullptr;
    static unsigned int* rowmax = nullptr;
    if (!h) {
        void* p;
        cudaGetSymbolAddress(&p, g_h);      h  = (float*)p;
        cudaGetSymbolAddress(&p, g_z);      z  = (float*)p;
        cudaGetSymbolAddress(&p, g_m);      mM = (float*)p;
        cudaGetSymbolAddress(&p, g_s1);     s1 = (float*)p;
        cudaGetSymbolAddress(&p, g_s2);     s2 = (float*)p;
        cudaGetSymbolAddress(&p, g_rowmax); rowmax = (unsigned int*)p;
        cudaFuncSetAttribute((const void*)&mma_gemm<DIN, false>,
                             cudaFuncAttributeMaxDynamicSharedMemorySize, SMEM_DYN);
        cudaFuncSetAttribute((const void*)&mma_gemm<DH, false>,
                             cudaFuncAttributeMaxDynamicSharedMemorySize, SMEM_DYN);
        cudaFuncSetAttribute((const void*)&mma_gemm<DOUT, true>,
                             cudaFuncAttributeMaxDynamicSharedMemorySize, SMEM_DYN);
    }

    // |c|^2 per codeword + state reset
    c2_init_kernel<<<KCB, 256>>>(codebook, s2);

    // h = latents @ W1^T + b1   (BF16x9 6-pass mma)
    mma_gemm<DIN, false><<<dim3(DH / 128, NROWS / 128), 256, SMEM_DYN>>>(
        latents, W1, b1, h, DH, nullptr);
    // h = gelu(layernorm(h))
    ln_kernel<DH, true, false><<<NROWS, 256>>>(h, g1, be1, nullptr);

    // z = h @ W2^T + b2
    mma_gemm<DH, false><<<dim3(DOUT / 128, NROWS / 128), 256, SMEM_DYN>>>(
        h, W2, b2, z, DOUT, nullptr);
    // z = layernorm(z); s1 = sum(z^2) per row
    ln_kernel<DOUT, false, true><<<NROWS, 256>>>(z, g2, be2, s1);

    // approx dot-product matrix m (bf16 3-pass) + per-row max
    mma_gemm<DOUT, true><<<dim3(KCB / 128, NROWS / 128), 256, SMEM_DYN>>>(
        z, codebook, nullptr, mM, KCB, rowmax);

    // candidate selection + exact-chain rescoring (R4-passing numerics)
    select_kernel<<<NROWS, 256>>>();
    rescore_kernel<<<NROWS, CAND_CAP>>>(codebook);

    // out = codebook[idx]
    gather_kernel<<<NROWS, 256>>>(codebook, out);
}